// round 10
// baseline (speedup 1.0000x reference)
#include <cuda_runtime.h>
#include <cuda_fp16.h>
#include <cstdint>

// ================= problem constants =================
constexpr int B_ROWS = 65536;
constexpr int LDIM   = 1024;
constexpr int COMB   = 1024;

// ================= tiling =================
constexpr int TM   = 128;            // batch rows per CTA (1 CTA/SM)
constexpr int N1C  = 128;
constexpr int KB   = 32;             // K per chunk (2 x k16 mma steps)
constexpr int NN1  = LDIM / N1C;     // 8
constexpr int NN1H = NN1 / 2;        // 4 per CTA (pair half)
constexpr int NKC  = COMB / KB;      // 32
constexpr int NSC  = N1C / KB;       // 4
constexpr int NIT  = NKC + NSC;      // 36
constexpr int S_H  = NN1H * NIT;     // 144
constexpr int MSLABS = B_ROWS / TM;  // 512 (128-row slabs)
constexpr int GRID   = MSLABS * 2;   // 1024 CTAs -> 6.92 waves
constexpr int NTHR   = 512;          // 16 warps: 4 wm x 4 wn, 32x32 tiles
constexpr int RING   = 6;            // prefetch distance 5

// ================= SMEM (.b32 = half2 units) =================
constexpr int ACH = 2048;                    // A chunk: [kk2][mt8][lane32][reg4] (8 KB)
constexpr int WCH = 2048;                    // W chunk: [nt16][kk2][lane32][reg2] (8 KB)
constexpr int SM_AB = 0;                     // RING x 2048
constexpr int SM_WB = RING * ACH;            // 12288
constexpr int SM_Q  = SM_WB + RING * WCH;    // 24576; Q: 4 chunks x 2048
constexpr int SMEM_U32 = SM_Q + 4 * ACH;     // 32768
constexpr int SMEM_BYTES = SMEM_U32 * 4;     // 131072
static_assert(SMEM_BYTES <= 232448, "smem");

// fragment-ordered fp16 weights + activations (built by prep kernels)
__device__ __align__(16) uint32_t g_W1frag[NN1 * NKC * WCH];            // 2 MB
__device__ __align__(16) uint32_t g_W2frag[NN1 * NSC * WCH];            // 256 KB
__device__ __align__(16) uint32_t g_Afrag[(size_t)MSLABS * NKC * ACH];  // 134 MB
__device__ __align__(16) float g_part[(size_t)GRID * NTHR * 32];        // 64 MB
__device__ unsigned g_cnt[MSLABS];   // zero-init; finisher resets each run

// ================= helpers =================
__device__ __forceinline__ uint32_t smem_u32(const void* p) {
    uint32_t a;
    asm("{ .reg .u64 t; cvta.to.shared.u64 t, %1; cvt.u32.u64 %0, t; }" : "=r"(a) : "l"(p));
    return a;
}
__device__ __forceinline__ uint32_t pack2(float a, float b) {
    __half2 h = __floats2half2_rn(a, b);
    return *reinterpret_cast<uint32_t*>(&h);
}
__device__ __forceinline__ float fast_tanh(float x) {
    float r;
    asm("tanh.approx.f32 %0, %1;" : "=f"(r) : "f"(x));
    return r;
}
__device__ __forceinline__ void cp16(uint32_t saddr, const uint32_t* gptr) {
    asm volatile("cp.async.cg.shared.global [%0], [%1], 16;"
                 :: "r"(saddr), "l"((unsigned long long)__cvta_generic_to_global(gptr)) : "memory");
}
__device__ __forceinline__ void cp_commit() { asm volatile("cp.async.commit_group;" ::: "memory"); }
__device__ __forceinline__ void cp_wait4()  { asm volatile("cp.async.wait_group 4;"  ::: "memory"); }
__device__ __forceinline__ void cp_wait0()  { asm volatile("cp.async.wait_group 0;"  ::: "memory"); }

__device__ __forceinline__ void mma16(float (&d)[4], const uint32_t (&a)[4], const uint32_t (&b)[2]) {
    asm volatile(
        "mma.sync.aligned.m16n8k16.row.col.f32.f16.f16.f32 "
        "{%0,%1,%2,%3},{%4,%5,%6,%7},{%8,%9},{%0,%1,%2,%3};"
        : "+f"(d[0]), "+f"(d[1]), "+f"(d[2]), "+f"(d[3])
        : "r"(a[0]), "r"(a[1]), "r"(a[2]), "r"(a[3]), "r"(b[0]), "r"(b[1]));
}

// one K=32 chunk (2 x k16), 32x32 warp tile on a 128-row CTA tile.
// abase: [kk2][mt8][lane32][areg4]; wb: [nt16][kk2][lane32][breg2]
__device__ __forceinline__ void mma_chunk(const uint32_t* __restrict__ abase,
                                          const uint32_t* __restrict__ wb,
                                          int wm, int wn, int lane, float (&acc)[2][4][4]) {
#pragma unroll
    for (int kk = 0; kk < 2; ++kk) {
        uint32_t af[2][4];
#pragma unroll
        for (int mt = 0; mt < 2; ++mt) {
            const uint4 v = *reinterpret_cast<const uint4*>(
                abase + (((kk * 8 + wm * 2 + mt) * 32 + lane) << 2));
            af[mt][0] = v.x; af[mt][1] = v.y; af[mt][2] = v.z; af[mt][3] = v.w;
        }
        uint32_t bf[4][2];
#pragma unroll
        for (int nt = 0; nt < 4; ++nt) {
            const uint2 v = *reinterpret_cast<const uint2*>(
                wb + ((((wn * 4 + nt) * 2 + kk) * 32 + lane) << 1));
            bf[nt][0] = v.x; bf[nt][1] = v.y;
        }
#pragma unroll
        for (int mt = 0; mt < 2; ++mt)
#pragma unroll
            for (int nt = 0; nt < 4; ++nt) mma16(acc[mt][nt], af[mt], bf[nt]);
    }
}

// ================= prep: Toeplitz expand + fragment pack (fp16) =================
__global__ void prep_w_kernel(const float* __restrict__ W1,
                              const float* __restrict__ Wsl,
                              const float* __restrict__ Wint) {
    const int f = blockIdx.x * 256 + threadIdx.x;
    const int T1 = NN1 * NKC * WCH;
    if (f < T1) {
        const int blk = f >> 11, r = f & 2047;
        const int n1 = blk >> 5, kc = blk & 31;
        const int reg = r & 1, lane = (r >> 1) & 31, kk = (r >> 6) & 1, nt = (r >> 7) & 15;
        const int n = n1 * 128 + nt * 8 + (lane >> 2);
        const int k = kc * 32 + kk * 16 + 2 * (lane & 3) + reg * 8;
        auto toep = [&](int kx) -> float {
            const int t = 1023 - n + kx;
            return (t < 1024) ? W1[(size_t)(1023 - t) * COMB] : W1[t - 1023];
        };
        g_W1frag[f] = pack2(toep(k), toep(k + 1));
    } else {
        const int f2 = f - T1;
        if (f2 < NN1 * NSC * WCH) {
            const int blk = f2 >> 11, r = f2 & 2047;
            const int n1 = blk >> 2, sc = blk & 3;
            const int reg = r & 1, lane = (r >> 1) & 31, kk = (r >> 6) & 1, nt = (r >> 7) & 15;
            const int n = nt * 8 + (lane >> 2);
            const int k = n1 * 128 + sc * 32 + kk * 16 + 2 * (lane & 3) + reg * 8;
            const float* src = (n < 64) ? Wsl + (size_t)n * LDIM : Wint + (size_t)(n - 64) * LDIM;
            g_W2frag[f2] = pack2(src[k], src[k + 1]);
        }
    }
}

// A frag: [slab128][kc][kk2][mt8][lane32][reg4]; .b32 packs A[row][k],A[row][k+1]
// row = slab*128 + mt*16 + (lane>>2) + (reg&1)*8; k = kc*32 + kk*16 + 2*(lane&3) + (reg>>1)*8
__global__ void prep_a_kernel(const float* __restrict__ xf, const float* __restrict__ he) {
    const size_t i = (size_t)blockIdx.x * 256 + threadIdx.x;
    uint32_t q = (uint32_t)i;
    const int reg  = q & 3;   q >>= 2;
    const int lane = q & 31;  q >>= 5;
    const int mt   = q & 7;   q >>= 3;
    const int kk   = q & 1;   q >>= 1;
    const int kc   = q & 31;  q >>= 5;
    const int slab = q;       // 0..511
    const int row = slab * 128 + mt * 16 + (lane >> 2) + (reg & 1) * 8;
    const int k   = kc * 32 + kk * 16 + 2 * (lane & 3) + (reg >> 1) * 8;
    const float* src = (k < 64) ? xf + (size_t)row * 64 + k
                                : he + (size_t)row * 960 + (k - 64);
    g_Afrag[i] = pack2(src[0], src[1]);
}

// ================= fused main kernel (TM=128, 16 warps, pair-split over n1) =================
__global__ void __launch_bounds__(NTHR, 1)
fused_kernel(const float* __restrict__ b1, const float* __restrict__ bs,
             const float* __restrict__ bi, float* __restrict__ out) {
    extern __shared__ uint32_t sm[];
    const uint32_t smb = smem_u32(sm);
    const int tid = threadIdx.x, lane = tid & 31, wid = tid >> 5;
    const int wm = wid & 3, wn = wid >> 2;   // 4x4 warp grid, 32x32 tiles
    const int bid  = blockIdx.x;
    const int mslab = bid >> 1;              // 128-row slab (0..511)
    const int half  = bid & 1;               // n1 half
    const int m0 = mslab * TM;

    float acc1[2][4][4];
    float acc2[2][4][4];
#pragma unroll
    for (int a = 0; a < 2; ++a)
#pragma unroll
        for (int b = 0; b < 4; ++b)
#pragma unroll
            for (int c = 0; c < 4; ++c) acc2[a][b][c] = 0.f;

    // stage iteration sp into ring slot sp%RING (512 threads: 1 cp16 each per buffer)
    auto fetch = [&](int sp) {
        const int n1p = half * NN1H + sp / NIT, posp = sp % NIT;
        const int slot = sp % RING;
        const uint32_t* wsrc = (posp < NKC)
            ? g_W1frag + ((size_t)(n1p * NKC + posp) * WCH)
            : g_W2frag + ((size_t)(n1p * NSC + (posp - NKC)) * WCH);
        cp16(smb + (uint32_t)((SM_WB + slot * WCH + tid * 4) << 2), wsrc + tid * 4);
        if (posp < NKC) {
            const uint32_t* asrc = g_Afrag + ((size_t)mslab * NKC + posp) * ACH;
            cp16(smb + (uint32_t)((SM_AB + slot * ACH + tid * 4) << 2), asrc + tid * 4);
        }
    };

    // prologue: 5 stages in flight
    fetch(0); cp_commit();
    fetch(1); cp_commit();
    fetch(2); cp_commit();
    fetch(3); cp_commit();
    fetch(4); cp_commit();

    for (int s = 0; s < S_H; ++s) {
        cp_wait4();
        __syncthreads();

        const int sp = s + 5;
        if (sp < S_H) fetch(sp);
        cp_commit();

        const int n1l = s / NIT, pos = s % NIT;
        const int n1g = half * NN1H + n1l;
        const int slot = s % RING;
        if (pos < NKC) {
            if (pos == 0) {
#pragma unroll
                for (int a = 0; a < 2; ++a)
#pragma unroll
                    for (int b = 0; b < 4; ++b)
#pragma unroll
                        for (int c = 0; c < 4; ++c) acc1[a][b][c] = 0.f;
            }
            mma_chunk(sm + SM_AB + slot * ACH, sm + SM_WB + slot * WCH, wm, wn, lane, acc1);
            if (pos == NKC - 1) {
                // epilogue1: q = fp16(relu(acc1 + b1)) -> SMEM in A-frag layout
                const float* b1p = b1 + n1g * 128 + wn * 32;
                const int t = lane & 3;
#pragma unroll
                for (int nt = 0; nt < 4; ++nt) {
                    const float2 bv = *reinterpret_cast<const float2*>(b1p + nt * 8 + t * 2);
#pragma unroll
                    for (int mt = 0; mt < 2; ++mt) {
                        const int mtq = wm * 2 + mt;           // 0..7
                        const float x0 = fmaxf(acc1[mt][nt][0] + bv.x, 0.f);
                        const float x1 = fmaxf(acc1[mt][nt][1] + bv.y, 0.f);
                        const float x2 = fmaxf(acc1[mt][nt][2] + bv.x, 0.f);
                        const float x3 = fmaxf(acc1[mt][nt][3] + bv.y, 0.f);
                        uint2 u;
                        u.x = pack2(x0, x1);
                        u.y = pack2(x2, x3);
                        uint32_t* dst = sm + SM_Q + wn * ACH
                                      + ((((nt >> 1) * 8 + mtq) * 32 + lane) << 2) + 2 * (nt & 1);
                        *reinterpret_cast<uint2*>(dst) = u;
                    }
                }
            }
        } else {
            mma_chunk(sm + SM_Q + (pos - NKC) * ACH, sm + SM_WB + slot * WCH, wm, wn, lane, acc2);
        }
    }
    cp_wait0();

    // ---- pair reduction: store partial acc2, second arriver finishes ----
    {
        float* wp = g_part + ((size_t)bid * NTHR + tid) * 32;
#pragma unroll
        for (int mt = 0; mt < 2; ++mt)
#pragma unroll
            for (int nt = 0; nt < 4; ++nt) {
                float4 v;
                v.x = acc2[mt][nt][0]; v.y = acc2[mt][nt][1];
                v.z = acc2[mt][nt][2]; v.w = acc2[mt][nt][3];
                *reinterpret_cast<float4*>(wp + (mt * 4 + nt) * 4) = v;
            }
        __threadfence();
        __syncthreads();
        if (tid == 0) {
            unsigned old = atomicAdd(&g_cnt[mslab], 1u);
            sm[SM_Q] = old;
        }
        __syncthreads();
        const unsigned old = sm[SM_Q];
        if (old == 0u) return;   // first arriver: partner finishes
        __threadfence();
        const float* pp = g_part + ((size_t)(bid ^ 1) * NTHR + tid) * 32;
#pragma unroll
        for (int mt = 0; mt < 2; ++mt)
#pragma unroll
            for (int nt = 0; nt < 4; ++nt) {
                const float4 v = *reinterpret_cast<const float4*>(pp + (mt * 4 + nt) * 4);
                acc2[mt][nt][0] += v.x; acc2[mt][nt][1] += v.y;
                acc2[mt][nt][2] += v.z; acc2[mt][nt][3] += v.w;
            }
    }

    // ---- final epilogue (finisher only): acc2 -> (tanh(x+bs) | x+bi) ----
    {
        const int g = lane >> 2, t = lane & 3;
        const int seg = wn >> 1;                 // 0: slope, 1: intercept
        const int cb  = (wn & 1) * 32;
        const float* bvecs = seg ? bi : bs;
        float* obase = out + (seg ? (size_t)B_ROWS * 64 : 0);
#pragma unroll
        for (int nt = 0; nt < 4; ++nt) {
            const int Cl = cb + nt * 8 + t * 2;
            const float2 bv = *reinterpret_cast<const float2*>(bvecs + Cl);
#pragma unroll
            for (int mt = 0; mt < 2; ++mt) {
#pragma unroll
                for (int rp = 0; rp < 2; ++rp) {
                    const int R = wm * 32 + mt * 16 + g + rp * 8;   // 0..127
                    float x0 = acc2[mt][nt][rp * 2 + 0] + bv.x;
                    float x1 = acc2[mt][nt][rp * 2 + 1] + bv.y;
                    if (seg == 0) { x0 = fast_tanh(x0); x1 = fast_tanh(x1); }
                    float2 o; o.x = x0; o.y = x1;
                    *reinterpret_cast<float2*>(obase + (size_t)(m0 + R) * 64 + Cl) = o;
                }
            }
        }
    }
    __syncthreads();
    if (tid == 0) g_cnt[mslab] = 0u;
}

// ================= launch =================
extern "C" void kernel_launch(void* const* d_in, const int* in_sizes, int n_in,
                              void* d_out, int out_size) {
    const float* xf = (const float*)d_in[0];
    const float* he = (const float*)d_in[1];
    const float* W1 = (const float*)d_in[2];
    const float* b1 = (const float*)d_in[3];
    const float* Ws = (const float*)d_in[4];
    const float* bs = (const float*)d_in[5];
    const float* Wi = (const float*)d_in[6];
    const float* bi = (const float*)d_in[7];
    float* out = (float*)d_out;

    static bool attr_set = false;
    if (!attr_set) {
        cudaFuncSetAttribute(fused_kernel, cudaFuncAttributeMaxDynamicSharedMemorySize, SMEM_BYTES);
        attr_set = true;
    }

    const int prep_w_total = NN1 * NKC * WCH + NN1 * NSC * WCH;   // 589824
    prep_w_kernel<<<(prep_w_total + 255) / 256, 256>>>(W1, Ws, Wi);
    const size_t prep_a_total = (size_t)MSLABS * NKC * ACH;       // 33554432
    prep_a_kernel<<<(unsigned)(prep_a_total / 256), 256>>>(xf, he);
    fused_kernel<<<GRID, NTHR, SMEM_BYTES>>>(b1, bs, bi, out);
}

// round 11
// speedup vs baseline: 1.4048x; 1.4048x over previous
#include <cuda_runtime.h>
#include <cuda_fp16.h>
#include <cstdint>

// ================= problem constants =================
constexpr int B_ROWS = 65536;
constexpr int LDIM   = 1024;
constexpr int COMB   = 1024;

// ================= tiling =================
constexpr int TM   = 64;             // batch rows per CTA (2 CTAs/SM)
constexpr int N1C  = 128;
constexpr int KB   = 64;             // K per chunk (4 x k16 mma steps)
constexpr int NN1  = LDIM / N1C;     // 8
constexpr int NN1H = NN1 / 2;        // 4 per CTA
constexpr int NKC  = COMB / KB;      // 16
constexpr int NSC  = N1C / KB;       // 2
constexpr int NIT  = NKC + NSC;      // 18
constexpr int S_H  = NN1H * NIT;     // 72 iterations per CTA
constexpr int MSLABS = B_ROWS / TM;  // 1024 (64-row slabs)
constexpr int GRID   = MSLABS * 2;   // 2048
constexpr int NTHR   = 256;          // 8 warps: 2 wm x 4 wn, 32x32 tiles
constexpr int RING   = 4;            // prefetch distance 3

// ================= SMEM (.b32 = half2 units) =================
constexpr int ACH = 2048;                    // A chunk: [kk4][mt4][lane32][reg4] (8 KB)
constexpr int WCH = 4096;                    // W chunk: [nt16][kk4][lane32][reg2] (16 KB)
constexpr int SM_AB = 0;                     // RING x 2048
constexpr int SM_WB = RING * ACH;            // 8192
constexpr int SM_Q  = SM_WB + RING * WCH;    // 24576; Q: 2 chunks x 2048
constexpr int SMEM_U32 = SM_Q + 2 * ACH;     // 28672
constexpr int SMEM_BYTES = SMEM_U32 * 4;     // 114688
static_assert(SMEM_BYTES <= 116224, "smem per CTA (2/SM)");

// fragment-ordered fp16 weights + activations (built by prep kernels)
__device__ __align__(16) uint32_t g_W1frag[NN1 * NKC * WCH];            // 2 MB
__device__ __align__(16) uint32_t g_W2frag[NN1 * NSC * WCH];            // 256 KB
__device__ __align__(16) uint32_t g_Afrag[(size_t)MSLABS * NKC * ACH];  // 134 MB
__device__ __align__(16) float g_part[(size_t)GRID * NTHR * 32];        // 64 MB
__device__ unsigned g_cnt[MSLABS];   // zero-init; finisher resets each run

// ================= helpers =================
__device__ __forceinline__ uint32_t smem_u32(const void* p) {
    uint32_t a;
    asm("{ .reg .u64 t; cvta.to.shared.u64 t, %1; cvt.u32.u64 %0, t; }" : "=r"(a) : "l"(p));
    return a;
}
__device__ __forceinline__ uint32_t pack2(float a, float b) {
    __half2 h = __floats2half2_rn(a, b);
    return *reinterpret_cast<uint32_t*>(&h);
}
__device__ __forceinline__ float fast_tanh(float x) {
    float r;
    asm("tanh.approx.f32 %0, %1;" : "=f"(r) : "f"(x));
    return r;
}
__device__ __forceinline__ void cp16(uint32_t saddr, const uint32_t* gptr) {
    asm volatile("cp.async.cg.shared.global [%0], [%1], 16;"
                 :: "r"(saddr), "l"((unsigned long long)__cvta_generic_to_global(gptr)) : "memory");
}
__device__ __forceinline__ void cp_commit() { asm volatile("cp.async.commit_group;" ::: "memory"); }
__device__ __forceinline__ void cp_wait2()  { asm volatile("cp.async.wait_group 2;"  ::: "memory"); }
__device__ __forceinline__ void cp_wait0()  { asm volatile("cp.async.wait_group 0;"  ::: "memory"); }

__device__ __forceinline__ void mma16(float (&d)[4], const uint32_t (&a)[4], const uint32_t (&b)[2]) {
    asm volatile(
        "mma.sync.aligned.m16n8k16.row.col.f32.f16.f16.f32 "
        "{%0,%1,%2,%3},{%4,%5,%6,%7},{%8,%9},{%0,%1,%2,%3};"
        : "+f"(d[0]), "+f"(d[1]), "+f"(d[2]), "+f"(d[3])
        : "r"(a[0]), "r"(a[1]), "r"(a[2]), "r"(a[3]), "r"(b[0]), "r"(b[1]));
}

// one K=64 chunk (4 x k16), 32x32 warp tile on 64-row CTA tile.
// abase: [kk4][mt4][lane32][areg4]; wb: [nt16][kk4][lane32][breg2]
__device__ __forceinline__ void mma_chunk(const uint32_t* __restrict__ abase,
                                          const uint32_t* __restrict__ wb,
                                          int wm, int wn, int lane, float (&acc)[2][4][4]) {
#pragma unroll
    for (int kk = 0; kk < 4; ++kk) {
        uint32_t af[2][4];
#pragma unroll
        for (int mt = 0; mt < 2; ++mt) {
            const uint4 v = *reinterpret_cast<const uint4*>(
                abase + (((kk * 4 + wm * 2 + mt) * 32 + lane) << 2));
            af[mt][0] = v.x; af[mt][1] = v.y; af[mt][2] = v.z; af[mt][3] = v.w;
        }
        uint32_t bf[4][2];
#pragma unroll
        for (int nt = 0; nt < 4; ++nt) {
            const uint2 v = *reinterpret_cast<const uint2*>(
                wb + ((((wn * 4 + nt) * 4 + kk) * 32 + lane) << 1));
            bf[nt][0] = v.x; bf[nt][1] = v.y;
        }
#pragma unroll
        for (int mt = 0; mt < 2; ++mt)
#pragma unroll
            for (int nt = 0; nt < 4; ++nt) mma16(acc[mt][nt], af[mt], bf[nt]);
    }
}

// ================= prep: Toeplitz expand + fragment pack (fp16, KB=64) =================
// W chunk layout [nt16][kk4][lane32][reg2]; element packs W[n][k],W[n][k+1]
// n = nt*8 + (lane>>2) [+n1*128 for W1]; k = base + kk*16 + 2*(lane&3) + reg*8
__global__ void prep_w_kernel(const float* __restrict__ W1,
                              const float* __restrict__ Wsl,
                              const float* __restrict__ Wint) {
    const int f = blockIdx.x * 256 + threadIdx.x;
    const int T1 = NN1 * NKC * WCH;
    if (f < T1) {
        const int blk = f >> 12, r = f & 4095;
        const int n1 = blk >> 4, kc = blk & 15;
        const int reg = r & 1, lane = (r >> 1) & 31, kk = (r >> 6) & 3, nt = (r >> 8) & 15;
        const int n = n1 * 128 + nt * 8 + (lane >> 2);
        const int k = kc * 64 + kk * 16 + 2 * (lane & 3) + reg * 8;
        auto toep = [&](int kx) -> float {
            const int t = 1023 - n + kx;
            return (t < 1024) ? W1[(size_t)(1023 - t) * COMB] : W1[t - 1023];
        };
        g_W1frag[f] = pack2(toep(k), toep(k + 1));
    } else {
        const int f2 = f - T1;
        if (f2 < NN1 * NSC * WCH) {
            const int blk = f2 >> 12, r = f2 & 4095;
            const int n1 = blk >> 1, sc = blk & 1;
            const int reg = r & 1, lane = (r >> 1) & 31, kk = (r >> 6) & 3, nt = (r >> 8) & 15;
            const int n = nt * 8 + (lane >> 2);
            const int k = n1 * 128 + sc * 64 + kk * 16 + 2 * (lane & 3) + reg * 8;
            const float* src = (n < 64) ? Wsl + (size_t)n * LDIM : Wint + (size_t)(n - 64) * LDIM;
            g_W2frag[f2] = pack2(src[k], src[k + 1]);
        }
    }
}

// A frag: [slab64][kc16][kk4][mt4][lane32][reg4]; packs A[row][k],A[row][k+1]
// row = slab*64 + mt*16 + (lane>>2) + (reg&1)*8; k = kc*64 + kk*16 + 2*(lane&3) + (reg>>1)*8
__global__ void prep_a_kernel(const float* __restrict__ xf, const float* __restrict__ he) {
    const size_t i = (size_t)blockIdx.x * 256 + threadIdx.x;
    uint32_t q = (uint32_t)i;
    const int reg  = q & 3;   q >>= 2;
    const int lane = q & 31;  q >>= 5;
    const int mt   = q & 3;   q >>= 2;
    const int kk   = q & 3;   q >>= 2;
    const int kc   = q & 15;  q >>= 4;
    const int slab = q;       // 0..1023
    const int row = slab * 64 + mt * 16 + (lane >> 2) + (reg & 1) * 8;
    const int k   = kc * 64 + kk * 16 + 2 * (lane & 3) + (reg >> 1) * 8;
    const float* src = (k < 64) ? xf + (size_t)row * 64 + k
                                : he + (size_t)row * 960 + (k - 64);
    g_Afrag[i] = pack2(src[0], src[1]);   // k even -> k,k+1 same segment
}

// ================= fused main kernel =================
__global__ void __launch_bounds__(NTHR, 2)
fused_kernel(const float* __restrict__ b1, const float* __restrict__ bs,
             const float* __restrict__ bi, float* __restrict__ out) {
    extern __shared__ uint32_t sm[];
    const uint32_t smb = smem_u32(sm);
    const int tid = threadIdx.x, lane = tid & 31, wid = tid >> 5;
    const int wm = wid & 1, wn = wid >> 1;   // 2x4 warp grid, 32x32 tiles
    const int bid  = blockIdx.x;
    const int mslab = bid >> 1;
    const int half  = bid & 1;
    const int m0 = mslab * TM;

    float acc1[2][4][4];
    float acc2[2][4][4];
#pragma unroll
    for (int a = 0; a < 2; ++a)
#pragma unroll
        for (int b = 0; b < 4; ++b)
#pragma unroll
            for (int c = 0; c < 4; ++c) acc2[a][b][c] = 0.f;

    // stage iteration sp into ring slot sp%RING (4 W cp16 + 2 A cp16 per thread)
    auto fetch = [&](int sp) {
        const int n1p = half * NN1H + sp / NIT, posp = sp % NIT;
        const int slot = sp % RING;
        const uint32_t* wsrc = (posp < NKC)
            ? g_W1frag + ((size_t)(n1p * NKC + posp) * WCH)
            : g_W2frag + ((size_t)(n1p * NSC + (posp - NKC)) * WCH);
        const uint32_t wdst = smb + (uint32_t)((SM_WB + slot * WCH + tid * 4) << 2);
#pragma unroll
        for (int i = 0; i < 4; ++i) cp16(wdst + i * 4096, wsrc + tid * 4 + i * 1024);
        if (posp < NKC) {
            const uint32_t* asrc = g_Afrag + ((size_t)mslab * NKC + posp) * ACH;
            const uint32_t adst = smb + (uint32_t)((SM_AB + slot * ACH + tid * 4) << 2);
#pragma unroll
            for (int i = 0; i < 2; ++i) cp16(adst + i * 4096, asrc + tid * 4 + i * 1024);
        }
    };

    // prologue: 3 stages in flight
    fetch(0); cp_commit();
    fetch(1); cp_commit();
    fetch(2); cp_commit();

    for (int s = 0; s < S_H; ++s) {
        cp_wait2();          // group s complete (s+1, s+2 in flight)
        __syncthreads();     // visibility + ring slot (s+3)%RING free

        const int sp = s + 3;
        if (sp < S_H) fetch(sp);
        cp_commit();

        const int n1l = s / NIT, pos = s % NIT;
        const int n1g = half * NN1H + n1l;
        const int slot = s % RING;
        if (pos < NKC) {
            if (pos == 0) {
#pragma unroll
                for (int a = 0; a < 2; ++a)
#pragma unroll
                    for (int b = 0; b < 4; ++b)
#pragma unroll
                        for (int c = 0; c < 4; ++c) acc1[a][b][c] = 0.f;
            }
            mma_chunk(sm + SM_AB + slot * ACH, sm + SM_WB + slot * WCH, wm, wn, lane, acc1);
            if (pos == NKC - 1) {
                // epilogue1: q = fp16(relu(acc1 + b1)) -> Q SMEM in A-frag layout.
                // dest: chunk = wn>>1, kk_q = (wn&1)*2 + (nt>>1), mtq = wm*2+mt,
                //       lane' = lane, regs {2*(nt&1), 2*(nt&1)+1}
                const float* b1p = b1 + n1g * 128 + wn * 32;
                const int t = lane & 3;
#pragma unroll
                for (int nt = 0; nt < 4; ++nt) {
                    const float2 bv = *reinterpret_cast<const float2*>(b1p + nt * 8 + t * 2);
#pragma unroll
                    for (int mt = 0; mt < 2; ++mt) {
                        const int mtq = wm * 2 + mt;
                        const int kkq = (wn & 1) * 2 + (nt >> 1);
                        const float x0 = fmaxf(acc1[mt][nt][0] + bv.x, 0.f);
                        const float x1 = fmaxf(acc1[mt][nt][1] + bv.y, 0.f);
                        const float x2 = fmaxf(acc1[mt][nt][2] + bv.x, 0.f);
                        const float x3 = fmaxf(acc1[mt][nt][3] + bv.y, 0.f);
                        uint2 u;
                        u.x = pack2(x0, x1);   // rows g,   reg 2*(nt&1)
                        u.y = pack2(x2, x3);   // rows g+8, reg 2*(nt&1)+1
                        uint32_t* dst = sm + SM_Q + (wn >> 1) * ACH
                                      + (((kkq * 4 + mtq) * 32 + lane) << 2) + 2 * (nt & 1);
                        *reinterpret_cast<uint2*>(dst) = u;
                    }
                }
            }
        } else {
            mma_chunk(sm + SM_Q + (pos - NKC) * ACH, sm + SM_WB + slot * WCH, wm, wn, lane, acc2);
        }
    }
    cp_wait0();

    // ---- pair reduction: store partial acc2, second arriver finishes ----
    {
        float* wp = g_part + ((size_t)bid * NTHR + tid) * 32;
#pragma unroll
        for (int mt = 0; mt < 2; ++mt)
#pragma unroll
            for (int nt = 0; nt < 4; ++nt) {
                float4 v;
                v.x = acc2[mt][nt][0]; v.y = acc2[mt][nt][1];
                v.z = acc2[mt][nt][2]; v.w = acc2[mt][nt][3];
                *reinterpret_cast<float4*>(wp + (mt * 4 + nt) * 4) = v;
            }
        __threadfence();
        __syncthreads();
        if (tid == 0) {
            unsigned old = atomicAdd(&g_cnt[mslab], 1u);
            sm[SM_Q] = old;
        }
        __syncthreads();
        const unsigned old = sm[SM_Q];
        if (old == 0u) return;   // first arriver: partner finishes
        __threadfence();
        const float* pp = g_part + ((size_t)(bid ^ 1) * NTHR + tid) * 32;
#pragma unroll
        for (int mt = 0; mt < 2; ++mt)
#pragma unroll
            for (int nt = 0; nt < 4; ++nt) {
                const float4 v = *reinterpret_cast<const float4*>(pp + (mt * 4 + nt) * 4);
                acc2[mt][nt][0] += v.x; acc2[mt][nt][1] += v.y;
                acc2[mt][nt][2] += v.z; acc2[mt][nt][3] += v.w;
            }
    }

    // ---- final epilogue (finisher only): acc2 -> (tanh(x+bs) | x+bi) ----
    {
        const int g = lane >> 2, t = lane & 3;
        const int seg = wn >> 1;                 // 0: slope, 1: intercept
        const int cb  = (wn & 1) * 32;
        const float* bvecs = seg ? bi : bs;
        float* obase = out + (seg ? (size_t)B_ROWS * 64 : 0);
#pragma unroll
        for (int nt = 0; nt < 4; ++nt) {
            const int Cl = cb + nt * 8 + t * 2;
            const float2 bv = *reinterpret_cast<const float2*>(bvecs + Cl);
#pragma unroll
            for (int mt = 0; mt < 2; ++mt) {
#pragma unroll
                for (int rp = 0; rp < 2; ++rp) {
                    const int R = wm * 32 + mt * 16 + g + rp * 8;   // 0..63
                    float x0 = acc2[mt][nt][rp * 2 + 0] + bv.x;
                    float x1 = acc2[mt][nt][rp * 2 + 1] + bv.y;
                    if (seg == 0) { x0 = fast_tanh(x0); x1 = fast_tanh(x1); }
                    float2 o; o.x = x0; o.y = x1;
                    *reinterpret_cast<float2*>(obase + (size_t)(m0 + R) * 64 + Cl) = o;
                }
            }
        }
    }
    __syncthreads();
    if (tid == 0) g_cnt[mslab] = 0u;
}

// ================= launch =================
extern "C" void kernel_launch(void* const* d_in, const int* in_sizes, int n_in,
                              void* d_out, int out_size) {
    const float* xf = (const float*)d_in[0];
    const float* he = (const float*)d_in[1];
    const float* W1 = (const float*)d_in[2];
    const float* b1 = (const float*)d_in[3];
    const float* Ws = (const float*)d_in[4];
    const float* bs = (const float*)d_in[5];
    const float* Wi = (const float*)d_in[6];
    const float* bi = (const float*)d_in[7];
    float* out = (float*)d_out;

    static bool attr_set = false;
    if (!attr_set) {
        cudaFuncSetAttribute(fused_kernel, cudaFuncAttributeMaxDynamicSharedMemorySize, SMEM_BYTES);
        attr_set = true;
    }

    const int prep_w_total = NN1 * NKC * WCH + NN1 * NSC * WCH;   // 589824
    prep_w_kernel<<<(prep_w_total + 255) / 256, 256>>>(W1, Ws, Wi);
    const size_t prep_a_total = (size_t)MSLABS * NKC * ACH;       // 33554432
    prep_a_kernel<<<(unsigned)(prep_a_total / 256), 256>>>(xf, he);
    fused_kernel<<<GRID, NTHR, SMEM_BYTES>>>(b1, bs, bi, out);
}

// round 12
// speedup vs baseline: 1.5195x; 1.0817x over previous
#include <cuda_runtime.h>
#include <cuda_fp16.h>
#include <cstdint>

// ================= problem constants =================
constexpr int B_ROWS = 65536;
constexpr int LDIM   = 1024;
constexpr int COMB   = 1024;

// ================= tiling =================
constexpr int TM   = 128;            // batch rows per CTA (1 CTA/SM)
constexpr int N1C  = 128;
constexpr int KB   = 64;             // K per chunk (4 x k16 mma steps)
constexpr int NN1  = LDIM / N1C;     // 8
constexpr int NN1H = NN1 / 2;        // 4 per CTA (pair half)
constexpr int NKC  = COMB / KB;      // 16
constexpr int NSC  = N1C / KB;       // 2
constexpr int NIT  = NKC + NSC;      // 18
constexpr int S_H  = NN1H * NIT;     // 72 iterations per CTA
constexpr int MSLABS = B_ROWS / TM;  // 512 (128-row slabs)
constexpr int GRID   = MSLABS * 2;   // 1024 CTAs -> 6.92 waves
constexpr int CT     = 512;          // compute threads: 16 warps, 4wm x 4wn, 32x32 tiles
constexpr int NTHR   = CT + 64;      // + warp16 (W fetch) + warp17 (A fetch)
constexpr int RING   = 6;            // mbarrier slot ring

// ================= SMEM (.b32 = half2 units) =================
constexpr int ACH = 4096;                    // A chunk: [kk4][mt8][lane32][reg4] (16 KB)
constexpr int WCH = 4096;                    // W chunk: [nt16][kk4][lane32][reg2] (16 KB)
constexpr int SM_AB = 0;                     // RING x 4096
constexpr int SM_WB = RING * ACH;            // 24576
constexpr int SM_Q  = SM_WB + RING * WCH;    // 49152; Q: 2 chunks x 4096
constexpr int SM_MB = SM_Q + 2 * ACH;        // 57344: FULL[6] then EMPTY[6], 2 u32 each
constexpr int SMEM_U32 = SM_MB + 2 * RING * 2;   // 57368
constexpr int SMEM_BYTES = SMEM_U32 * 4;         // 229472
static_assert(SMEM_BYTES <= 232448, "smem");

// fragment-ordered fp16 weights + activations (built by prep kernels)
__device__ __align__(16) uint32_t g_W1frag[NN1 * NKC * WCH];            // 2 MB
__device__ __align__(16) uint32_t g_W2frag[NN1 * NSC * WCH];            // 256 KB
__device__ __align__(16) uint32_t g_Afrag[(size_t)MSLABS * NKC * ACH];  // 134 MB
__device__ __align__(16) float g_part[(size_t)GRID * CT * 32];          // 64 MB
__device__ unsigned g_cnt[MSLABS];   // zero-init; finisher resets each run

// ================= helpers =================
__device__ __forceinline__ uint32_t smem_u32(const void* p) {
    uint32_t a;
    asm("{ .reg .u64 t; cvta.to.shared.u64 t, %1; cvt.u32.u64 %0, t; }" : "=r"(a) : "l"(p));
    return a;
}
__device__ __forceinline__ uint32_t pack2(float a, float b) {
    __half2 h = __floats2half2_rn(a, b);
    return *reinterpret_cast<uint32_t*>(&h);
}
__device__ __forceinline__ float fast_tanh(float x) {
    float r;
    asm("tanh.approx.f32 %0, %1;" : "=f"(r) : "f"(x));
    return r;
}
__device__ __forceinline__ void cp16(uint32_t saddr, const uint32_t* gptr) {
    asm volatile("cp.async.cg.shared.global [%0], [%1], 16;"
                 :: "r"(saddr), "l"((unsigned long long)__cvta_generic_to_global(gptr)) : "memory");
}
__device__ __forceinline__ void cp_commit() { asm volatile("cp.async.commit_group;" ::: "memory"); }
__device__ __forceinline__ void cp_wait3()  { asm volatile("cp.async.wait_group 3;"  ::: "memory"); }
__device__ __forceinline__ void cp_wait2()  { asm volatile("cp.async.wait_group 2;"  ::: "memory"); }
__device__ __forceinline__ void cp_wait1()  { asm volatile("cp.async.wait_group 1;"  ::: "memory"); }
__device__ __forceinline__ void cp_wait0()  { asm volatile("cp.async.wait_group 0;"  ::: "memory"); }

__device__ __forceinline__ void mbar_init(uint32_t a, uint32_t cnt) {
    asm volatile("mbarrier.init.shared.b64 [%0], %1;" :: "r"(a), "r"(cnt) : "memory");
}
__device__ __forceinline__ void mbar_arrive(uint32_t a) {
    asm volatile("mbarrier.arrive.shared.b64 _, [%0];" :: "r"(a) : "memory");
}
__device__ __forceinline__ void mbar_wait(uint32_t a, uint32_t ph) {
    asm volatile(
        "{\n\t.reg .pred P;\n\t"
        "W_%=:\n\t"
        "mbarrier.try_wait.parity.acquire.cta.shared::cta.b64 P, [%0], %1, 0x989680;\n\t"
        "@P bra D_%=;\n\t"
        "bra W_%=;\n\t"
        "D_%=:\n\t}"
        :: "r"(a), "r"(ph) : "memory");
}

__device__ __forceinline__ void mma16(float (&d)[4], const uint32_t (&a)[4], const uint32_t (&b)[2]) {
    asm volatile(
        "mma.sync.aligned.m16n8k16.row.col.f32.f16.f16.f32 "
        "{%0,%1,%2,%3},{%4,%5,%6,%7},{%8,%9},{%0,%1,%2,%3};"
        : "+f"(d[0]), "+f"(d[1]), "+f"(d[2]), "+f"(d[3])
        : "r"(a[0]), "r"(a[1]), "r"(a[2]), "r"(a[3]), "r"(b[0]), "r"(b[1]));
}

// one K=64 chunk (4 x k16), 32x32 warp tile on a 128-row CTA tile.
// abase: [kk4][mt8][lane32][areg4]; wb: [nt16][kk4][lane32][breg2]
__device__ __forceinline__ void mma_chunk(const uint32_t* __restrict__ abase,
                                          const uint32_t* __restrict__ wb,
                                          int wm, int wn, int lane, float (&acc)[2][4][4]) {
#pragma unroll
    for (int kk = 0; kk < 4; ++kk) {
        uint32_t af[2][4];
#pragma unroll
        for (int mt = 0; mt < 2; ++mt) {
            const uint4 v = *reinterpret_cast<const uint4*>(
                abase + (((kk * 8 + wm * 2 + mt) * 32 + lane) << 2));
            af[mt][0] = v.x; af[mt][1] = v.y; af[mt][2] = v.z; af[mt][3] = v.w;
        }
        uint32_t bf[4][2];
#pragma unroll
        for (int nt = 0; nt < 4; ++nt) {
            const uint2 v = *reinterpret_cast<const uint2*>(
                wb + ((((wn * 4 + nt) * 4 + kk) * 32 + lane) << 1));
            bf[nt][0] = v.x; bf[nt][1] = v.y;
        }
#pragma unroll
        for (int mt = 0; mt < 2; ++mt)
#pragma unroll
            for (int nt = 0; nt < 4; ++nt) mma16(acc[mt][nt], af[mt], bf[nt]);
    }
}

// ================= prep: Toeplitz expand + fragment pack (fp16, KB=64) =================
__global__ void prep_w_kernel(const float* __restrict__ W1,
                              const float* __restrict__ Wsl,
                              const float* __restrict__ Wint) {
    const int f = blockIdx.x * 256 + threadIdx.x;
    const int T1 = NN1 * NKC * WCH;
    if (f < T1) {
        const int blk = f >> 12, r = f & 4095;
        const int n1 = blk >> 4, kc = blk & 15;
        const int reg = r & 1, lane = (r >> 1) & 31, kk = (r >> 6) & 3, nt = (r >> 8) & 15;
        const int n = n1 * 128 + nt * 8 + (lane >> 2);
        const int k = kc * 64 + kk * 16 + 2 * (lane & 3) + reg * 8;
        auto toep = [&](int kx) -> float {
            const int t = 1023 - n + kx;
            return (t < 1024) ? W1[(size_t)(1023 - t) * COMB] : W1[t - 1023];
        };
        g_W1frag[f] = pack2(toep(k), toep(k + 1));
    } else {
        const int f2 = f - T1;
        if (f2 < NN1 * NSC * WCH) {
            const int blk = f2 >> 12, r = f2 & 4095;
            const int n1 = blk >> 1, sc = blk & 1;
            const int reg = r & 1, lane = (r >> 1) & 31, kk = (r >> 6) & 3, nt = (r >> 8) & 15;
            const int n = nt * 8 + (lane >> 2);
            const int k = n1 * 128 + sc * 64 + kk * 16 + 2 * (lane & 3) + reg * 8;
            const float* src = (n < 64) ? Wsl + (size_t)n * LDIM : Wint + (size_t)(n - 64) * LDIM;
            g_W2frag[f2] = pack2(src[k], src[k + 1]);
        }
    }
}

// A frag: [slab512][kc16][kk4][mt8][lane32][reg4]; packs A[row][k],A[row][k+1]
// row = slab*128 + mt*16 + (lane>>2) + (reg&1)*8; k = kc*64 + kk*16 + 2*(lane&3) + (reg>>1)*8
__global__ void prep_a_kernel(const float* __restrict__ xf, const float* __restrict__ he) {
    const size_t i = (size_t)blockIdx.x * 256 + threadIdx.x;
    uint32_t q = (uint32_t)i;
    const int reg  = q & 3;   q >>= 2;
    const int lane = q & 31;  q >>= 5;
    const int mt   = q & 7;   q >>= 3;
    const int kk   = q & 3;   q >>= 2;
    const int kc   = q & 15;  q >>= 4;
    const int slab = q;       // 0..511
    const int row = slab * 128 + mt * 16 + (lane >> 2) + (reg & 1) * 8;
    const int k   = kc * 64 + kk * 16 + 2 * (lane & 3) + (reg >> 1) * 8;
    const float* src = (k < 64) ? xf + (size_t)row * 64 + k
                                : he + (size_t)row * 960 + (k - 64);
    g_Afrag[i] = pack2(src[0], src[1]);   // k even -> k,k+1 same segment
}

// ================= fused main kernel: warp-specialized mbarrier pipeline =================
__global__ void __launch_bounds__(NTHR, 1)
fused_kernel(const float* __restrict__ b1, const float* __restrict__ bs,
             const float* __restrict__ bi, float* __restrict__ out) {
    extern __shared__ uint32_t sm[];
    const uint32_t smb = smem_u32(sm);
    const int tid = threadIdx.x, lane = tid & 31, wid = tid >> 5;
    const int bid  = blockIdx.x;
    const int mslab = bid >> 1;              // 128-row slab (0..511)
    const int half  = bid & 1;               // n1 half
    const int m0 = mslab * TM;

    // mbarrier byte addresses
    auto FULLB  = [&](int s) { return smb + (uint32_t)((SM_MB + s * 2) << 2); };
    auto EMPTYB = [&](int s) { return smb + (uint32_t)((SM_MB + (RING + s) * 2) << 2); };

    if (tid == 0) {
#pragma unroll
        for (int s = 0; s < RING; ++s) {
            mbar_init(FULLB(s), 2);    // 2 producer warps arrive (lane 0 each)
            mbar_init(EMPTYB(s), 16);  // 16 compute warps arrive (lane 0 each)
        }
    }
    __syncthreads();

    if (wid < 16) {
        // ================= consumers: 16 compute warps, 4x4 grid =================
        const int wm = wid & 3, wn = wid >> 2;
        float acc1[2][4][4];
        float acc2[2][4][4];
#pragma unroll
        for (int a = 0; a < 2; ++a)
#pragma unroll
            for (int b = 0; b < 4; ++b)
#pragma unroll
                for (int c = 0; c < 4; ++c) acc2[a][b][c] = 0.f;

        int cslot = 0, cphase = 0;
        int pos = 0, n1g = half * NN1H;
        for (int s = 0; s < S_H; ++s) {
            mbar_wait(FULLB(cslot), (uint32_t)cphase);
            if (pos < NKC) {
                if (pos == 0) {
#pragma unroll
                    for (int a = 0; a < 2; ++a)
#pragma unroll
                        for (int b = 0; b < 4; ++b)
#pragma unroll
                            for (int c = 0; c < 4; ++c) acc1[a][b][c] = 0.f;
                }
                mma_chunk(sm + SM_AB + cslot * ACH, sm + SM_WB + cslot * WCH,
                          wm, wn, lane, acc1);
                if (lane == 0) mbar_arrive(EMPTYB(cslot));
                if (pos == NKC - 1) {
                    // epilogue1: q = fp16(relu(acc1 + b1)) -> Q SMEM in A-frag layout
                    const float* b1p = b1 + n1g * 128 + wn * 32;
                    const int t = lane & 3;
#pragma unroll
                    for (int nt = 0; nt < 4; ++nt) {
                        const float2 bv = *reinterpret_cast<const float2*>(b1p + nt * 8 + t * 2);
#pragma unroll
                        for (int mt = 0; mt < 2; ++mt) {
                            const int mtq = wm * 2 + mt;                 // 0..7
                            const int kkq = (wn & 1) * 2 + (nt >> 1);    // 0..3
                            const float x0 = fmaxf(acc1[mt][nt][0] + bv.x, 0.f);
                            const float x1 = fmaxf(acc1[mt][nt][1] + bv.y, 0.f);
                            const float x2 = fmaxf(acc1[mt][nt][2] + bv.x, 0.f);
                            const float x3 = fmaxf(acc1[mt][nt][3] + bv.y, 0.f);
                            uint2 u;
                            u.x = pack2(x0, x1);   // rows g,   reg 2*(nt&1)
                            u.y = pack2(x2, x3);   // rows g+8, reg 2*(nt&1)+1
                            uint32_t* dst = sm + SM_Q + (wn >> 1) * ACH
                                          + (((kkq * 8 + mtq) * 32 + lane) << 2) + 2 * (nt & 1);
                            *reinterpret_cast<uint2*>(dst) = u;
                        }
                    }
                    // all compute warps must finish Q writes before GEMM2 reads
                    asm volatile("bar.sync 1, 512;" ::: "memory");
                }
            } else {
                mma_chunk(sm + SM_Q + (pos - NKC) * ACH, sm + SM_WB + cslot * WCH,
                          wm, wn, lane, acc2);
                if (lane == 0) mbar_arrive(EMPTYB(cslot));
            }
            if (++cslot == RING) { cslot = 0; cphase ^= 1; }
            if (++pos == NIT) { pos = 0; ++n1g; }
        }

        // pair reduction + epilogue below (shared path)
    } else {
        // ================= producers: warp16 = W, warp17 = A =================
        const bool isW = (wid == 16);
        int sslot = 0;                 // fill slot cursor
        int eslot = 0, ephase = 0;     // empty-wait cursor (starts at sp=RING)
        int aslot = 0;                 // FULL-arrival cursor (for sp-3)
        int pos = 0, n1p = half * NN1H;
        for (int sp = 0; sp < S_H; ++sp) {
            if (sp >= RING) {
                mbar_wait(EMPTYB(eslot), (uint32_t)ephase);
                if (++eslot == RING) { eslot = 0; ephase ^= 1; }
            }
            if (isW) {
                const uint32_t* wsrc = (pos < NKC)
                    ? g_W1frag + ((size_t)(n1p * NKC + pos) * WCH)
                    : g_W2frag + ((size_t)(n1p * NSC + (pos - NKC)) * WCH);
                const uint32_t wdst = smb + (uint32_t)((SM_WB + sslot * WCH + lane * 4) << 2);
#pragma unroll
                for (int i = 0; i < 32; ++i)
                    cp16(wdst + i * 512, wsrc + lane * 4 + i * 128);
            } else {
                if (pos < NKC) {
                    const uint32_t* asrc = g_Afrag + ((size_t)mslab * NKC + pos) * ACH;
                    const uint32_t adst = smb + (uint32_t)((SM_AB + sslot * ACH + lane * 4) << 2);
#pragma unroll
                    for (int i = 0; i < 32; ++i)
                        cp16(adst + i * 512, asrc + lane * 4 + i * 128);
                }
            }
            cp_commit();   // one group per sp (possibly empty for A on GEMM2 iters)
            if (sp >= 3) {
                cp_wait3();
                if (lane == 0) mbar_arrive(FULLB(aslot));
                if (++aslot == RING) aslot = 0;
            }
            if (++sslot == RING) sslot = 0;
            if (++pos == NIT) { pos = 0; ++n1p; }
        }
        // drain: arrive for the last 3 groups
        cp_wait2(); if (lane == 0) mbar_arrive(FULLB(aslot)); if (++aslot == RING) aslot = 0;
        cp_wait1(); if (lane == 0) mbar_arrive(FULLB(aslot)); if (++aslot == RING) aslot = 0;
        cp_wait0(); if (lane == 0) mbar_arrive(FULLB(aslot));
    }

    // ---- pair reduction: store partial acc2, second arriver finishes ----
    // (acc2 only meaningful for tid < CT; fetch warps just participate in barriers)
    {
        if (tid < CT) {
            // NOTE: compute warps' acc2 is in scope only inside the if-branch above,
            // so re-declare storage here via a small shim: we re-materialize through
            // a per-thread copy kept in registers by structuring the code below.
        }
    }
    // To keep acc2 in scope, the reduction is implemented inside the consumer branch
    // via goto-free duplication: see reduce_and_output() pattern below.
    // --- actual implementation: consumers fall through with acc2 via this block ---
    // (handled by the code below using a union trick is unnecessary: we instead
    //  re-enter a common path with acc2 passed through registers)
    // The code is restructured: consumers jump here with acc2 alive.
    // Implementation detail: we inline everything in the consumer branch instead.
    // (fetch warps do the barrier-only version)
    if (wid >= 16) {
        __threadfence();
        __syncthreads();                     // matches consumers' barrier
        __syncthreads();                     // matches consumers' 2nd barrier
        const unsigned old = sm[SM_Q];
        if (old == 0u) return;
        __syncthreads();                     // matches consumers' final barrier
        return;
    }

    // consumers: wid < 16 — acc2 not in scope here due to branch structure,
    // so the reduction was moved INTO the consumer branch? No — acc2 IS out of
    // scope. Fix: re-run with acc2 hoisted. See hoisted declaration below.
    return;
}

// The above kernel has a scoping problem for acc2 — final version with acc2
// hoisted to function scope:
__global__ void __launch_bounds__(NTHR, 1)
fused_kernel_v2(const float* __restrict__ b1, const float* __restrict__ bs,
                const float* __restrict__ bi, float* __restrict__ out) {
    extern __shared__ uint32_t sm[];
    const uint32_t smb = smem_u32(sm);
    const int tid = threadIdx.x, lane = tid & 31, wid = tid >> 5;
    const int bid  = blockIdx.x;
    const int mslab = bid >> 1;
    const int half  = bid & 1;
    const int m0 = mslab * TM;

    auto FULLB  = [&](int s) { return smb + (uint32_t)((SM_MB + s * 2) << 2); };
    auto EMPTYB = [&](int s) { return smb + (uint32_t)((SM_MB + (RING + s) * 2) << 2); };

    if (tid == 0) {
#pragma unroll
        for (int s = 0; s < RING; ++s) {
            mbar_init(FULLB(s), 2);
            mbar_init(EMPTYB(s), 16);
        }
    }
    __syncthreads();

    float acc2[2][4][4];
#pragma unroll
    for (int a = 0; a < 2; ++a)
#pragma unroll
        for (int b = 0; b < 4; ++b)
#pragma unroll
            for (int c = 0; c < 4; ++c) acc2[a][b][c] = 0.f;
    const int wm = wid & 3, wn = wid >> 2;   // valid for wid<16 only

    if (wid < 16) {
        float acc1[2][4][4];
        int cslot = 0, cphase = 0;
        int pos = 0, n1g = half * NN1H;
        for (int s = 0; s < S_H; ++s) {
            mbar_wait(FULLB(cslot), (uint32_t)cphase);
            if (pos < NKC) {
                if (pos == 0) {
#pragma unroll
                    for (int a = 0; a < 2; ++a)
#pragma unroll
                        for (int b = 0; b < 4; ++b)
#pragma unroll
                            for (int c = 0; c < 4; ++c) acc1[a][b][c] = 0.f;
                }
                mma_chunk(sm + SM_AB + cslot * ACH, sm + SM_WB + cslot * WCH,
                          wm, wn, lane, acc1);
                if (lane == 0) mbar_arrive(EMPTYB(cslot));
                if (pos == NKC - 1) {
                    const float* b1p = b1 + n1g * 128 + wn * 32;
                    const int t = lane & 3;
#pragma unroll
                    for (int nt = 0; nt < 4; ++nt) {
                        const float2 bv = *reinterpret_cast<const float2*>(b1p + nt * 8 + t * 2);
#pragma unroll
                        for (int mt = 0; mt < 2; ++mt) {
                            const int mtq = wm * 2 + mt;
                            const int kkq = (wn & 1) * 2 + (nt >> 1);
                            const float x0 = fmaxf(acc1[mt][nt][0] + bv.x, 0.f);
                            const float x1 = fmaxf(acc1[mt][nt][1] + bv.y, 0.f);
                            const float x2 = fmaxf(acc1[mt][nt][2] + bv.x, 0.f);
                            const float x3 = fmaxf(acc1[mt][nt][3] + bv.y, 0.f);
                            uint2 u;
                            u.x = pack2(x0, x1);
                            u.y = pack2(x2, x3);
                            uint32_t* dst = sm + SM_Q + (wn >> 1) * ACH
                                          + (((kkq * 8 + mtq) * 32 + lane) << 2) + 2 * (nt & 1);
                            *reinterpret_cast<uint2*>(dst) = u;
                        }
                    }
                    asm volatile("bar.sync 1, 512;" ::: "memory");
                }
            } else {
                mma_chunk(sm + SM_Q + (pos - NKC) * ACH, sm + SM_WB + cslot * WCH,
                          wm, wn, lane, acc2);
                if (lane == 0) mbar_arrive(EMPTYB(cslot));
            }
            if (++cslot == RING) { cslot = 0; cphase ^= 1; }
            if (++pos == NIT) { pos = 0; ++n1g; }
        }
    } else {
        const bool isW = (wid == 16);
        int sslot = 0;
        int eslot = 0, ephase = 0;
        int aslot = 0;
        int pos = 0, n1p = half * NN1H;
        for (int sp = 0; sp < S_H; ++sp) {
            if (sp >= RING) {
                mbar_wait(EMPTYB(eslot), (uint32_t)ephase);
                if (++eslot == RING) { eslot = 0; ephase ^= 1; }
            }
            if (isW) {
                const uint32_t* wsrc = (pos < NKC)
                    ? g_W1frag + ((size_t)(n1p * NKC + pos) * WCH)
                    : g_W2frag + ((size_t)(n1p * NSC + (pos - NKC)) * WCH);
                const uint32_t wdst = smb + (uint32_t)((SM_WB + sslot * WCH + lane * 4) << 2);
#pragma unroll
                for (int i = 0; i < 32; ++i)
                    cp16(wdst + i * 512, wsrc + lane * 4 + i * 128);
            } else if (pos < NKC) {
                const uint32_t* asrc = g_Afrag + ((size_t)mslab * NKC + pos) * ACH;
                const uint32_t adst = smb + (uint32_t)((SM_AB + sslot * ACH + lane * 4) << 2);
#pragma unroll
                for (int i = 0; i < 32; ++i)
                    cp16(adst + i * 512, asrc + lane * 4 + i * 128);
            }
            cp_commit();
            if (sp >= 3) {
                cp_wait3();
                if (lane == 0) mbar_arrive(FULLB(aslot));
                if (++aslot == RING) aslot = 0;
            }
            if (++sslot == RING) sslot = 0;
            if (++pos == NIT) { pos = 0; ++n1p; }
        }
        cp_wait2(); if (lane == 0) mbar_arrive(FULLB(aslot)); if (++aslot == RING) aslot = 0;
        cp_wait1(); if (lane == 0) mbar_arrive(FULLB(aslot)); if (++aslot == RING) aslot = 0;
        cp_wait0(); if (lane == 0) mbar_arrive(FULLB(aslot));
    }

    // ---- pair reduction: store partial acc2, second arriver finishes ----
    if (tid < CT) {
        float* wp = g_part + ((size_t)bid * CT + tid) * 32;
#pragma unroll
        for (int mt = 0; mt < 2; ++mt)
#pragma unroll
            for (int nt = 0; nt < 4; ++nt) {
                float4 v;
                v.x = acc2[mt][nt][0]; v.y = acc2[mt][nt][1];
                v.z = acc2[mt][nt][2]; v.w = acc2[mt][nt][3];
                *reinterpret_cast<float4*>(wp + (mt * 4 + nt) * 4) = v;
            }
    }
    __threadfence();
    __syncthreads();
    if (tid == 0) {
        unsigned old = atomicAdd(&g_cnt[mslab], 1u);
        sm[SM_Q] = old;
    }
    __syncthreads();
    const unsigned old = sm[SM_Q];
    if (old == 0u) return;   // first arriver: partner finishes
    __threadfence();
    if (tid < CT) {
        const float* pp = g_part + ((size_t)(bid ^ 1) * CT + tid) * 32;
#pragma unroll
        for (int mt = 0; mt < 2; ++mt)
#pragma unroll
            for (int nt = 0; nt < 4; ++nt) {
                const float4 v = *reinterpret_cast<const float4*>(pp + (mt * 4 + nt) * 4);
                acc2[mt][nt][0] += v.x; acc2[mt][nt][1] += v.y;
                acc2[mt][nt][2] += v.z; acc2[mt][nt][3] += v.w;
            }

        // ---- final epilogue (finisher compute threads): acc2 -> (tanh(x+bs) | x+bi) ----
        const int g = lane >> 2, t = lane & 3;
        const int seg = wn >> 1;                 // 0: slope, 1: intercept
        const int cb  = (wn & 1) * 32;
        const float* bvecs = seg ? bi : bs;
        float* obase = out + (seg ? (size_t)B_ROWS * 64 : 0);
#pragma unroll
        for (int nt = 0; nt < 4; ++nt) {
            const int Cl = cb + nt * 8 + t * 2;
            const float2 bv = *reinterpret_cast<const float2*>(bvecs + Cl);
#pragma unroll
            for (int mt = 0; mt < 2; ++mt) {
#pragma unroll
                for (int rp = 0; rp < 2; ++rp) {
                    const int R = wm * 32 + mt * 16 + g + rp * 8;   // 0..127
                    float x0 = acc2[mt][nt][rp * 2 + 0] + bv.x;
                    float x1 = acc2[mt][nt][rp * 2 + 1] + bv.y;
                    if (seg == 0) { x0 = fast_tanh(x0); x1 = fast_tanh(x1); }
                    float2 o; o.x = x0; o.y = x1;
                    *reinterpret_cast<float2*>(obase + (size_t)(m0 + R) * 64 + Cl) = o;
                }
            }
        }
    }
    __syncthreads();
    if (tid == 0) g_cnt[mslab] = 0u;
}

// ================= launch =================
extern "C" void kernel_launch(void* const* d_in, const int* in_sizes, int n_in,
                              void* d_out, int out_size) {
    const float* xf = (const float*)d_in[0];
    const float* he = (const float*)d_in[1];
    const float* W1 = (const float*)d_in[2];
    const float* b1 = (const float*)d_in[3];
    const float* Ws = (const float*)d_in[4];
    const float* bs = (const float*)d_in[5];
    const float* Wi = (const float*)d_in[6];
    const float* bi = (const float*)d_in[7];
    float* out = (float*)d_out;

    static bool attr_set = false;
    if (!attr_set) {
        cudaFuncSetAttribute(fused_kernel_v2, cudaFuncAttributeMaxDynamicSharedMemorySize, SMEM_BYTES);
        attr_set = true;
    }

    const int prep_w_total = NN1 * NKC * WCH + NN1 * NSC * WCH;   // 589824
    prep_w_kernel<<<(prep_w_total + 255) / 256, 256>>>(W1, Ws, Wi);
    const size_t prep_a_total = (size_t)MSLABS * NKC * ACH;       // 33554432
    prep_a_kernel<<<(unsigned)(prep_a_total / 256), 256>>>(xf, he);
    fused_kernel_v2<<<GRID, NTHR, SMEM_BYTES>>>(b1, bs, bi, out);
}